// round 1
// baseline (speedup 1.0000x reference)
#include <cuda_runtime.h>
#include <math.h>

// ---------------- problem constants ----------------
#define B_  2
#define L_  16
#define C_  64
#define S_  64
#define W_  128
#define R_  32
#define H_  32
#define BL_ (B_*L_)          // 32
#define SW_ (S_*W_)          // 8192
#define CR_ (C_*R_)          // 2048
#define PLANES_ (BL_*C_)     // 2048
#define NELEM_ (PLANES_*SW_) // 16777216

// ---------------- device scratch ----------------
__device__ float g_lam_re[CR_], g_lam_im[CR_], g_gamma[CR_];
__device__ float g_ctx[BL_*C_];
__device__ float g_mod_re[BL_*CR_], g_mod_im[BL_*CR_];
__device__ float g_u_re[BL_*CR_],  g_u_im[BL_*CR_];
__device__ float g_h_re[BL_*CR_],  g_h_im[BL_*CR_];
__device__ float g_P[C_*C_*9], g_Q[C_*C_*9];
__device__ float g_A[C_*C_*9], g_Bk[C_*C_*9];
__device__ float g_T[C_*9], g_c0[C_];
__device__ float g_yr[NELEM_];
__device__ float g_yi[NELEM_];
__device__ float g_fused[NELEM_];

// ---------------- helpers ----------------
__device__ __forceinline__ float blockReduceSum(float v, float* sbuf) {
    int lane = threadIdx.x & 31, warp = threadIdx.x >> 5;
    #pragma unroll
    for (int o = 16; o > 0; o >>= 1) v += __shfl_down_sync(0xffffffffu, v, o);
    if (lane == 0) sbuf[warp] = v;
    __syncthreads();
    int nw = blockDim.x >> 5;
    v = (threadIdx.x < nw) ? sbuf[threadIdx.x] : 0.f;
    if (warp == 0) {
        #pragma unroll
        for (int o = 16; o > 0; o >>= 1) v += __shfl_down_sync(0xffffffffu, v, o);
    }
    return v;  // valid in thread 0
}

// ---------------- K1: poles ----------------
__global__ void k_poles(const float* __restrict__ nu_log, const float* __restrict__ th_log,
                        const float* __restrict__ dnu, const float* __restrict__ dth) {
    int i = blockIdx.x * 256 + threadIdx.x;
    if (i >= CR_) return;
    float nu = expf(nu_log[i] + dnu[i]);
    float th = expf(th_log[i] + dth[i]);
    float el = expf(-nu);
    g_lam_re[i] = el * cosf(th);
    g_lam_im[i] = el * sinf(th);
    g_gamma[i]  = sqrtf(fmaxf(1.f - el * el, 1e-6f));
}

// ---------------- K7a: P,Q = fuse ∘ conv kernels, const bias ----------------
// grid 64 (o), block 576 (c*9+t)
__global__ void k_pq(const float* __restrict__ fuse_k, const float* __restrict__ convr_k,
                     const float* __restrict__ convi_k, const float* __restrict__ convr_b,
                     const float* __restrict__ convi_b, const float* __restrict__ fuse_b) {
    int o = blockIdx.x, tid = threadIdx.x;
    __shared__ float sF1[C_], sF2[C_];
    if (tid < 64)       sF1[tid]      = fuse_k[o*128 + tid];
    else if (tid < 128) sF2[tid - 64] = fuse_k[o*128 + tid];
    __syncthreads();
    float p = 0.f, q = 0.f;
    for (int m = 0; m < C_; m++) {
        p += sF1[m] * convr_k[m*576 + tid];
        q += sF2[m] * convi_k[m*576 + tid];
    }
    g_P[o*576 + tid] = p;
    g_Q[o*576 + tid] = q;
    if (tid == 0) {
        float v = fuse_b[o];
        for (int m = 0; m < C_; m++) v += sF1[m]*convr_b[m] + sF2[m]*convi_b[m];
        g_c0[o] = v;
    }
}

// ---------------- K7b: fold proj into combined kernels A,B and border taps T ----------------
// grid 64 (o), block 576 (c'*9+t)
__global__ void k_ab(const float* __restrict__ Wr, const float* __restrict__ Wi,
                     const float* __restrict__ br, const float* __restrict__ bi) {
    int o = blockIdx.x, tid = threadIdx.x;
    int cp = tid / 9, t = tid % 9;
    __shared__ float sP[576], sQ[576];
    sP[tid] = g_P[o*576 + tid];
    sQ[tid] = g_Q[o*576 + tid];
    __syncthreads();
    float a = 0.f, bb = 0.f;
    for (int cc = 0; cc < C_; cc++) {
        float p = sP[cc*9 + t], q = sQ[cc*9 + t];
        float wr = Wr[cc*C_ + cp], wi = Wi[cc*C_ + cp];
        a  += p * wr + q * wi;
        bb += -p * wi + q * wr;
    }
    g_A[o*576 + tid]  = a;
    g_Bk[o*576 + tid] = bb;
    if (tid < 9) {
        float tt = 0.f;
        for (int cc = 0; cc < C_; cc++)
            tt += sP[cc*9 + tid]*br[cc] + sQ[cc*9 + tid]*bi[cc];
        g_T[o*9 + tid] = tt;
    }
}

// ---------------- K2: spatial-mean context ----------------
// grid PLANES_ (b,l,c), block 256
__global__ void k_ctx(const float* __restrict__ x) {
    __shared__ float sbuf[8];
    int blc = blockIdx.x;
    const float* xp = x + (size_t)blc * SW_;
    float s = 0.f;
    for (int i = threadIdx.x; i < SW_; i += 256) s += xp[i];
    s = blockReduceSum(s, sbuf);
    if (threadIdx.x == 0) g_ctx[blc] = s * (1.f / (float)SW_);
}

// ---------------- K3: MLP -> modulation m = gamma*(1+forcing) ----------------
// grid BL_, block 256
__global__ void k_mlp(const float* __restrict__ w1, const float* __restrict__ b1,
                      const float* __restrict__ w2, const float* __restrict__ b2,
                      const float* __restrict__ fscale) {
    __shared__ float sc[C_], shid[H_], sf[CR_*2];
    int bl = blockIdx.x, tid = threadIdx.x;
    if (tid < C_) sc[tid] = g_ctx[bl*C_ + tid];
    __syncthreads();
    if (tid < H_) {
        float v = b1[tid];
        for (int cc = 0; cc < C_; cc++) v += sc[cc] * w1[cc*H_ + tid];
        shid[tid] = tanhf(v);
    }
    __syncthreads();
    for (int k = tid; k < CR_*2; k += 256) {
        float v = b2[k];
        #pragma unroll
        for (int j = 0; j < H_; j++) v += shid[j] * w2[j*(CR_*2) + k];
        sf[k] = v;
    }
    __syncthreads();
    float fs = *fscale;
    for (int cr = tid; cr < CR_; cr += 256) {
        float ga = g_gamma[cr];
        g_mod_re[bl*CR_ + cr] = ga * (1.f + fs * sf[2*cr]);
        g_mod_im[bl*CR_ + cr] = ga * (fs * sf[2*cr + 1]);
    }
}

// ---------------- K4: low-rank projection u = mod * (x · conj(U) · conj(V)) ----------------
// grid PLANES_, block 128 (one thread per w). dyn smem: x(8192) + U4(4096) + V4(8192) + red(256)
#define SMEM_U_BYTES ((8192 + 4096 + 8192 + 256) * 4)
__global__ void k_u(const float* __restrict__ x,
                    const float* __restrict__ Ur, const float* __restrict__ Ui,
                    const float* __restrict__ Vr, const float* __restrict__ Vi) {
    extern __shared__ float sm[];
    float* sx   = sm;
    float* sU   = sm + 8192;
    float* sV   = sm + 8192 + 4096;
    float* sred = sm + 8192 + 4096 + 8192;
    int tid = threadIdx.x;
    int blc = blockIdx.x;
    int c = blc % C_;
    const float* xp = x + (size_t)blc * SW_;
    for (int i = tid; i < SW_; i += 128) sx[i] = xp[i];
    for (int i = tid; i < S_*R_; i += 128) {
        int s = i >> 5, r = i & 31;
        int off = s*64 + (r >> 1)*4 + (r & 1)*2;
        sU[off]     = Ur[c*S_*R_ + i];
        sU[off + 1] = Ui[c*S_*R_ + i];
    }
    for (int i = tid; i < W_*R_; i += 128) {
        int w = i >> 5, r = i & 31;
        int off = w*64 + (r >> 1)*4 + (r & 1)*2;
        sV[off]     = Vr[c*W_*R_ + i];
        sV[off + 1] = Vi[c*W_*R_ + i];
    }
    __syncthreads();
    int w = tid, lane = tid & 31, warp = tid >> 5;
    const float4* u4base = reinterpret_cast<const float4*>(sU);
    const float4* v4base = reinterpret_cast<const float4*>(sV);
    for (int r2 = 0; r2 < 16; r2++) {
        float ar0 = 0, ai0 = 0, ar1 = 0, ai1 = 0;
        const float4* u4 = u4base + r2;
        #pragma unroll 8
        for (int s = 0; s < S_; s++) {
            float xv = sx[s*W_ + w];
            float4 u = u4[s*16];
            ar0 = fmaf(xv, u.x, ar0); ai0 = fmaf(xv, u.y, ai0);
            ar1 = fmaf(xv, u.z, ar1); ai1 = fmaf(xv, u.w, ai1);
        }
        float4 v = v4base[w*16 + r2];  // (Vr0,Vi0,Vr1,Vi1)
        float pr0 = ar0*v.x - ai0*v.y;
        float pi0 = -(ar0*v.y + ai0*v.x);
        float pr1 = ar1*v.z - ai1*v.w;
        float pi1 = -(ar1*v.w + ai1*v.z);
        #pragma unroll
        for (int o = 16; o > 0; o >>= 1) {
            pr0 += __shfl_down_sync(0xffffffffu, pr0, o);
            pi0 += __shfl_down_sync(0xffffffffu, pi0, o);
            pr1 += __shfl_down_sync(0xffffffffu, pr1, o);
            pi1 += __shfl_down_sync(0xffffffffu, pi1, o);
        }
        if (lane == 0) {
            int r = r2*2;
            sred[(warp*R_ + r)*2]     = pr0; sred[(warp*R_ + r)*2 + 1]     = pi0;
            sred[(warp*R_ + r + 1)*2] = pr1; sred[(warp*R_ + r + 1)*2 + 1] = pi1;
        }
    }
    __syncthreads();
    if (tid < R_) {
        int r = tid;
        float ur = 0, ui = 0;
        #pragma unroll
        for (int wp = 0; wp < 4; wp++) {
            ur += sred[(wp*R_ + r)*2];
            ui += sred[(wp*R_ + r)*2 + 1];
        }
        float mr = g_mod_re[blc*R_ + r], mi = g_mod_im[blc*R_ + r];
        g_u_re[blc*R_ + r] = mr*ur - mi*ui;
        g_u_im[blc*R_ + r] = mr*ui + mi*ur;
    }
}

// ---------------- K5: diagonal scan over L ----------------
// grid 16, block 256 -> 4096 threads = B*C*R
__global__ void k_scan() {
    int t = blockIdx.x * 256 + threadIdx.x;
    int b = t >> 11;        // / CR_
    int cr = t & (CR_ - 1);
    float lr = g_lam_re[cr], li = g_lam_im[cr];
    float hr = 0.f, hi = 0.f;
    #pragma unroll
    for (int l = 0; l < L_; l++) {
        int idx = (b*L_ + l)*CR_ + cr;
        float ur = g_u_re[idx], ui = g_u_im[idx];
        float nr = lr*hr - li*hi + ur;
        float ni = lr*hi + li*hr + ui;
        hr = nr; hi = ni;
        g_h_re[idx] = hr;
        g_h_im[idx] = hi;
    }
}

// ---------------- K6: reconstruct y = (h·U)·V ----------------
// grid PLANES_, block 512. dyn smem: U(4096) + Vpad(8448) + gpad(4224) + h(64)
#define SMEM_R_BYTES ((4096 + 8448 + 4224 + 64) * 4)
__global__ void k_recon(const float* __restrict__ Ur, const float* __restrict__ Ui,
                        const float* __restrict__ Vr, const float* __restrict__ Vi) {
    extern __shared__ float sm[];
    float* sU = sm;                       // [s*32+r] *2
    float* sV = sm + 4096;                // [(w*33+r)] *2
    float* sg = sm + 4096 + 8448;         // [(s*33+r)] *2
    float* sh = sm + 4096 + 8448 + 4224;  // [r] *2
    int tid = threadIdx.x;
    int blc = blockIdx.x;
    int c = blc % C_;
    if (tid < R_) {
        sh[tid*2]     = g_h_re[blc*R_ + tid];
        sh[tid*2 + 1] = g_h_im[blc*R_ + tid];
    }
    for (int i = tid; i < S_*R_; i += 512) {
        sU[i*2]     = Ur[c*S_*R_ + i];
        sU[i*2 + 1] = Ui[c*S_*R_ + i];
    }
    for (int i = tid; i < W_*R_; i += 512) {
        int w = i >> 5, r = i & 31;
        sV[(w*33 + r)*2]     = Vr[c*W_*R_ + i];
        sV[(w*33 + r)*2 + 1] = Vi[c*W_*R_ + i];
    }
    __syncthreads();
    for (int i = tid; i < S_*R_; i += 512) {
        int s = i >> 5, r = i & 31;
        float hr = sh[r*2], hi = sh[r*2 + 1];
        float ur = sU[i*2], ui = sU[i*2 + 1];
        sg[(s*33 + r)*2]     = hr*ur - hi*ui;
        sg[(s*33 + r)*2 + 1] = hr*ui + hi*ur;
    }
    __syncthreads();
    int s = tid >> 3, wg = tid & 7;
    float accr[16], acci[16];
    #pragma unroll
    for (int k = 0; k < 16; k++) { accr[k] = 0.f; acci[k] = 0.f; }
    const float2* g2 = reinterpret_cast<const float2*>(sg);
    const float2* v2 = reinterpret_cast<const float2*>(sV);
    #pragma unroll 2
    for (int r = 0; r < R_; r++) {
        float2 g = g2[s*33 + r];
        #pragma unroll
        for (int k = 0; k < 16; k++) {
            int w = wg + 8*k;
            float2 v = v2[w*33 + r];
            accr[k] = fmaf(g.x, v.x, fmaf(-g.y, v.y, accr[k]));
            acci[k] = fmaf(g.x, v.y, fmaf( g.y, v.x, acci[k]));
        }
    }
    float* pyr = g_yr + (size_t)blc*SW_ + s*W_ + wg;
    float* pyi = g_yi + (size_t)blc*SW_ + s*W_ + wg;
    #pragma unroll
    for (int k = 0; k < 16; k++) {
        pyr[8*k] = accr[k];
        pyi[8*k] = acci[k];
    }
}

// ---------------- K8: fused double 3x3 conv (proj+convs+fuse all folded) ----------------
// grid (BL_, 8 tiles, 8 o-tiles), block 256. 32x32 spatial tile, 8 out channels.
__global__ void __launch_bounds__(256) k_conv() {
    __shared__ float syr[34*36];
    __shared__ float syi[34*36];
    __shared__ float sA[8*9], sB[8*9], sT[8*9], sc0[8];
    int tid = threadIdx.x;
    int tx = tid & 31, ty = tid >> 5;
    int bl = blockIdx.x;
    int s0 = (blockIdx.y >> 2) * 32, w0 = (blockIdx.y & 3) * 32;
    int o0 = blockIdx.z * 8;
    if (tid < 72) sT[tid] = g_T[(o0 + tid/9)*9 + tid%9];
    if (tid < 8)  sc0[tid] = g_c0[o0 + tid];
    __syncthreads();
    float acc[4][8];
    int wglob = w0 + tx;
    #pragma unroll
    for (int p = 0; p < 4; p++) {
        int sglob = s0 + ty*4 + p;
        #pragma unroll
        for (int o = 0; o < 8; o++) acc[p][o] = sc0[o];
        #pragma unroll
        for (int dy = 0; dy < 3; dy++)
            #pragma unroll
            for (int dx = 0; dx < 3; dx++) {
                bool valid = ((unsigned)(sglob + dy - 1) < S_) && ((unsigned)(wglob + dx - 1) < W_);
                if (valid) {
                    #pragma unroll
                    for (int o = 0; o < 8; o++) acc[p][o] += sT[o*9 + dy*3 + dx];
                }
            }
    }
    const float* yrbase = g_yr + (size_t)bl * (C_*SW_);
    const float* yibase = g_yi + (size_t)bl * (C_*SW_);
    for (int ci = 0; ci < C_; ci++) {
        __syncthreads();
        for (int i = tid; i < 34*34; i += 256) {
            int row = i / 34, col = i % 34;
            int gs = s0 - 1 + row, gw = w0 - 1 + col;
            bool ok = ((unsigned)gs < S_) && ((unsigned)gw < W_);
            size_t gidx = (size_t)ci*SW_ + gs*W_ + gw;
            syr[row*36 + col] = ok ? yrbase[gidx] : 0.f;
            syi[row*36 + col] = ok ? yibase[gidx] : 0.f;
        }
        if (tid < 72) {
            sA[tid] = g_A [((o0 + tid/9)*C_ + ci)*9 + tid%9];
            sB[tid] = g_Bk[((o0 + tid/9)*C_ + ci)*9 + tid%9];
        }
        __syncthreads();
        #pragma unroll
        for (int t = 0; t < 9; t++) {
            int dy = t / 3, dx = t % 3;
            float a[8], b[8];
            #pragma unroll
            for (int o = 0; o < 8; o++) { a[o] = sA[o*9 + t]; b[o] = sB[o*9 + t]; }
            #pragma unroll
            for (int p = 0; p < 4; p++) {
                float xr = syr[(ty*4 + p + dy)*36 + tx + dx];
                float xi = syi[(ty*4 + p + dy)*36 + tx + dx];
                #pragma unroll
                for (int o = 0; o < 8; o++)
                    acc[p][o] = fmaf(a[o], xr, fmaf(b[o], xi, acc[p][o]));
            }
        }
    }
    float* outb = g_fused + (size_t)bl * (C_*SW_);
    #pragma unroll
    for (int p = 0; p < 4; p++) {
        int sglob = s0 + ty*4 + p;
        #pragma unroll
        for (int o = 0; o < 8; o++)
            outb[(size_t)(o0 + o)*SW_ + sglob*W_ + wglob] = acc[p][o];
    }
}

// ---------------- K9: LayerNorm over (S,W) + residual ----------------
// grid PLANES_, block 256
__global__ void k_ln(const float* __restrict__ x, const float* __restrict__ lng,
                     const float* __restrict__ lnb, float* __restrict__ out) {
    __shared__ float sbuf1[8], sbuf2[8];
    __shared__ float s_mu, s_rstd;
    int blc = blockIdx.x, tid = threadIdx.x;
    const float* fp = g_fused + (size_t)blc * SW_;
    float v[32];
    float sum = 0.f, sq = 0.f;
    #pragma unroll
    for (int k = 0; k < 32; k++) {
        float t = fp[tid + 256*k];
        v[k] = t; sum += t; sq += t*t;
    }
    float ts = blockReduceSum(sum, sbuf1);
    __syncthreads();
    float tq = blockReduceSum(sq, sbuf2);
    if (tid == 0) {
        float mu = ts * (1.f / (float)SW_);
        float var = tq * (1.f / (float)SW_) - mu*mu;
        s_mu = mu;
        s_rstd = rsqrtf(var + 1e-5f);
    }
    __syncthreads();
    float mu = s_mu, rstd = s_rstd;
    const float* xp = x + (size_t)blc * SW_;
    float* op = out + (size_t)blc * SW_;
    #pragma unroll
    for (int k = 0; k < 32; k++) {
        int i = tid + 256*k;
        op[i] = (v[k] - mu) * rstd * lng[i] + lnb[i] + xp[i];
    }
}

// ---------------- launch ----------------
extern "C" void kernel_launch(void* const* d_in, const int* in_sizes, int n_in,
                              void* d_out, int out_size) {
    const float* x         = (const float*)d_in[0];
    const float* nu_log    = (const float*)d_in[1];
    const float* theta_log = (const float*)d_in[2];
    const float* disp_nu   = (const float*)d_in[3];
    const float* disp_th   = (const float*)d_in[4];
    const float* mlp_w1    = (const float*)d_in[5];
    const float* mlp_b1    = (const float*)d_in[6];
    const float* mlp_w2    = (const float*)d_in[7];
    const float* mlp_b2    = (const float*)d_in[8];
    const float* fscale    = (const float*)d_in[9];
    const float* U_row_r   = (const float*)d_in[10];
    const float* U_row_i   = (const float*)d_in[11];
    const float* V_col_r   = (const float*)d_in[12];
    const float* V_col_i   = (const float*)d_in[13];
    const float* proj_W_r  = (const float*)d_in[14];
    const float* proj_W_i  = (const float*)d_in[15];
    const float* proj_b_r  = (const float*)d_in[16];
    const float* proj_b_i  = (const float*)d_in[17];
    const float* convr_k   = (const float*)d_in[18];
    const float* convr_b   = (const float*)d_in[19];
    const float* convi_k   = (const float*)d_in[20];
    const float* convi_b   = (const float*)d_in[21];
    const float* fuse_k    = (const float*)d_in[22];
    const float* fuse_b    = (const float*)d_in[23];
    const float* ln_g      = (const float*)d_in[24];
    const float* ln_b      = (const float*)d_in[25];
    float* out = (float*)d_out;

    cudaFuncSetAttribute(k_u,     cudaFuncAttributeMaxDynamicSharedMemorySize, SMEM_U_BYTES);
    cudaFuncSetAttribute(k_recon, cudaFuncAttributeMaxDynamicSharedMemorySize, SMEM_R_BYTES);

    k_poles<<<(CR_ + 255)/256, 256>>>(nu_log, theta_log, disp_nu, disp_th);
    k_pq<<<C_, 576>>>(fuse_k, convr_k, convi_k, convr_b, convi_b, fuse_b);
    k_ab<<<C_, 576>>>(proj_W_r, proj_W_i, proj_b_r, proj_b_i);
    k_ctx<<<PLANES_, 256>>>(x);
    k_mlp<<<BL_, 256>>>(mlp_w1, mlp_b1, mlp_w2, mlp_b2, fscale);
    k_u<<<PLANES_, 128, SMEM_U_BYTES>>>(x, U_row_r, U_row_i, V_col_r, V_col_i);
    k_scan<<<16, 256>>>();
    k_recon<<<PLANES_, 512, SMEM_R_BYTES>>>(U_row_r, U_row_i, V_col_r, V_col_i);
    k_conv<<<dim3(BL_, 8, 8), 256>>>();
    k_ln<<<PLANES_, 256>>>(x, ln_g, ln_b, out);
}